// round 5
// baseline (speedup 1.0000x reference)
#include <cuda_runtime.h>
#include <cstdint>

// MaxUnpooling2D as gather, 256-bit (v8.f32) loads/stores — sm_100a feature.
// updates/mask: [16,64,64,256] f32/i32; out: [16,128,128,256] f32.
// out[b,y,x,c] = (mask[b,y>>1,x>>1,c] == flat(b,y,x,c)) ? updates[...] : 0
//
// Thread handles one float8 (32B) of input -> 4 float8 outputs (2x2 window).
// Thread id t (float8 units), 2^21 threads:
//   c8 = t & 31 | w = (t>>5)&63 | h = (t>>11)&63 | b = t>>17
//   input float8 index == t (zero address math on loads).
// Output float8 base: o00 = b<<19 | h<<13 | w<<6 | c8
//   dx -> +32 float8 (one x step = 256 floats), dy -> +4096 float8.
// flat element index of lane 0 at output o: o*8.

__global__ __launch_bounds__(256, 8)
void max_unpool_gather8(const float* __restrict__ upd,
                        const float* __restrict__ mskf,
                        float* __restrict__ out)
{
    unsigned t = blockIdx.x * 256u + threadIdx.x;   // 0 .. 2^21-1

    const float* mp = mskf + (size_t)t * 8u;
    const float* up = upd  + (size_t)t * 8u;

    // Front-batched 256-bit loads (64B in flight per thread immediately).
    float g0,g1,g2,g3,g4,g5,g6,g7;      // mask bits (as f32 payload)
    float u0,u1,u2,u3,u4,u5,u6,u7;      // updates
    asm("ld.global.nc.v8.f32 {%0,%1,%2,%3,%4,%5,%6,%7}, [%8];"
        : "=f"(g0),"=f"(g1),"=f"(g2),"=f"(g3),
          "=f"(g4),"=f"(g5),"=f"(g6),"=f"(g7)
        : "l"(mp));
    asm("ld.global.nc.v8.f32 {%0,%1,%2,%3,%4,%5,%6,%7}, [%8];"
        : "=f"(u0),"=f"(u1),"=f"(u2),"=f"(u3),
          "=f"(u4),"=f"(u5),"=f"(u6),"=f"(u7)
        : "l"(up));

    int m0 = __float_as_int(g0), m1 = __float_as_int(g1);
    int m2 = __float_as_int(g2), m3 = __float_as_int(g3);
    int m4 = __float_as_int(g4), m5 = __float_as_int(g5);
    int m6 = __float_as_int(g6), m7 = __float_as_int(g7);

    unsigned c8 = t & 31u;
    unsigned w  = (t >> 5)  & 63u;
    unsigned h  = (t >> 11) & 63u;
    unsigned b  = t >> 17;

    unsigned o00 = (b << 19) | (h << 13) | (w << 6) | c8;   // float8 units

    #pragma unroll
    for (int dy = 0; dy < 2; ++dy) {
        #pragma unroll
        for (int dx = 0; dx < 2; ++dx) {
            unsigned o = o00 + (unsigned)(dy * 4096 + dx * 32);
            int f = (int)(o << 3);              // flat element idx of lane 0
            float r0 = (m0 == f    ) ? u0 : 0.0f;
            float r1 = (m1 == f + 1) ? u1 : 0.0f;
            float r2 = (m2 == f + 2) ? u2 : 0.0f;
            float r3 = (m3 == f + 3) ? u3 : 0.0f;
            float r4 = (m4 == f + 4) ? u4 : 0.0f;
            float r5 = (m5 == f + 5) ? u5 : 0.0f;
            float r6 = (m6 == f + 6) ? u6 : 0.0f;
            float r7 = (m7 == f + 7) ? u7 : 0.0f;
            float* po = out + ((size_t)o << 3);
            asm volatile("st.global.v8.f32 [%0], {%1,%2,%3,%4,%5,%6,%7,%8};"
                         :: "l"(po),
                            "f"(r0),"f"(r1),"f"(r2),"f"(r3),
                            "f"(r4),"f"(r5),"f"(r6),"f"(r7)
                         : "memory");
        }
    }
}

extern "C" void kernel_launch(void* const* d_in, const int* in_sizes, int n_in,
                              void* d_out, int out_size)
{
    const float* upd  = (const float*)d_in[0];
    const float* mskf = (const float*)d_in[1];   // int32 mask, loaded as bits
    float*       out  = (float*)d_out;

    // 16*64*64*256 input elems / 8 per thread = 2,097,152 threads.
    dim3 grid(2097152u / 256u);
    max_unpool_gather8<<<grid, 256>>>(upd, mskf, out);
}